// round 14
// baseline (speedup 1.0000x reference)
#include <cuda_runtime.h>
#include <cstddef>
#include <cstdint>

// Problem constants
#define PB 4
#define PN 16384
#define PM 16384
#define PK 16
#define PC 64
#define PO 64
#define PG 8

typedef unsigned long long ull;

// ---- f32x2 packed helpers (sm_103a FFMA2 path) ----
__device__ __forceinline__ void ffma2(ull& d, ull a, ull b, ull c) {
    asm("fma.rn.f32x2 %0, %1, %2, %3;" : "=l"(d) : "l"(a), "l"(b), "l"(c));
}
__device__ __forceinline__ void fadd2(ull& d, ull a, ull b) {
    asm("add.rn.f32x2 %0, %1, %2;" : "=l"(d) : "l"(a), "l"(b));
}
__device__ __forceinline__ ull pack2(float lo, float hi) {
    ull r; asm("mov.b64 %0, {%1, %2};" : "=l"(r) : "f"(lo), "f"(hi)); return r;
}
__device__ __forceinline__ float2 unpack2(ull v) {
    float2 f; asm("mov.b64 {%0, %1}, %2;" : "=f"(f.x), "=f"(f.y) : "l"(v)); return f;
}
__device__ __forceinline__ ull lds64(uint32_t a) {
    ull r; asm volatile("ld.shared.b64 %0, [%1];" : "=l"(r) : "r"(a)); return r;
}
__device__ __forceinline__ void lds128(ull& x, ull& y, uint32_t a) {
    asm volatile("ld.shared.v2.b64 {%0,%1}, [%2];" : "=l"(x), "=l"(y) : "r"(a));
}
__device__ __forceinline__ void sts128(uint32_t a, ull x, ull y) {
    asm volatile("st.shared.v2.b64 [%0], {%1,%2};" :: "r"(a), "l"(x), "l"(y) : "memory");
}
__device__ __forceinline__ void ldg128(ull& x, ull& y, const void* p) {
    asm volatile("ld.global.nc.v2.b64 {%0,%1}, [%2];" : "=l"(x), "=l"(y) : "l"(p));
}
__device__ __forceinline__ void stg128(void* p, ull x, ull y) {
    asm volatile("st.global.v2.b64 [%0], {%1,%2};" :: "l"(p), "l"(x), "l"(y) : "memory");
}

static __device__ float g_xv[PB * PN * PO];   // x_v [B,N,64]
static __device__ float g_a [PB * PN * PG];   // per-point logit precursor [B,N,8]
static __device__ float g_c [PB * PM * PG];   // per-center logit precursor [B,M,8]

// ---------------------------------------------------------------------------
// Kernel 1+2 merged (fold_kernel eliminated: each path recomputes its tiny
// weight folds in-block; the fold loads overlap the path's own cold loads).
// blocks [0,256): per-point precompute (2 pts/thread)
// blocks [256,768): per-center precompute (1 center/thread)
// ---------------------------------------------------------------------------
__global__ void __launch_bounds__(128, 2)
pc_kernel(const float* __restrict__ fea,
          const float* __restrict__ Wv,
          const float* __restrict__ bv,
          const float* __restrict__ Wq, const float* __restrict__ bq,
          const float* __restrict__ Wk, const float* __restrict__ bk,
          const float* __restrict__ cpe_w1, const float* __restrict__ cpe_s,
          const float* __restrict__ cpe_b,
          const float* __restrict__ cpe_w2, const float* __restrict__ cpe_b2,
          const float* __restrict__ we_w1, const float* __restrict__ we_s,
          const float* __restrict__ we_b,
          const float* __restrict__ center_pos,
          const float* __restrict__ center_fea) {
    __shared__ float su[4680];
    int tid = threadIdx.x;

    if (blockIdx.x < 256) {
        // ---------------- point path ----------------
        float* sWv  = su;            // 4096
        float* sWka = su + 4096;     // 512
        float* sbv  = su + 4608;     // 64
        float* sa0  = su + 4672;     // 8
        for (int i = tid; i < 4096; i += 128) sWv[i] = Wv[i];
        // in-block fold: sWka[c*8+g] = (Wk[c,:]·we_w1[:,g]) * we_s[g]
        {
            int c  = tid >> 1;
            int g0 = (tid & 1) * 4;
            float4 acc = make_float4(0.f, 0.f, 0.f, 0.f);
            #pragma unroll 8
            for (int o = 0; o < 64; o++) {
                float w = __ldg(Wk + c * 64 + o);
                float4 ww = *(const float4*)(we_w1 + o * 8 + g0);
                acc.x = fmaf(w, ww.x, acc.x); acc.y = fmaf(w, ww.y, acc.y);
                acc.z = fmaf(w, ww.z, acc.z); acc.w = fmaf(w, ww.w, acc.w);
            }
            float4 ws = *(const float4*)(we_s + g0);
            sWka[c * 8 + g0 + 0] = acc.x * ws.x;
            sWka[c * 8 + g0 + 1] = acc.y * ws.y;
            sWka[c * 8 + g0 + 2] = acc.z * ws.z;
            sWka[c * 8 + g0 + 3] = acc.w * ws.w;
        }
        if (tid < 64) sbv[tid] = bv[tid];
        if (tid < 8) {
            float a0 = 0.f;
            #pragma unroll 8
            for (int o = 0; o < 64; o++)
                a0 = fmaf(__ldg(bk + o), we_w1[o * 8 + tid], a0);
            sa0[tid] = a0 * we_s[tid];
        }
        __syncthreads();

        uint32_t aWv = (uint32_t)__cvta_generic_to_shared(sWv);
        uint32_t aKa = (uint32_t)__cvta_generic_to_shared(sWka);
        uint32_t aBv = (uint32_t)__cvta_generic_to_shared(sbv);
        uint32_t aA0 = (uint32_t)__cvta_generic_to_shared(sa0);

        int gp0 = (blockIdx.x * 128 + tid) * 2;   // two adjacent points
        int b = gp0 >> 14;
        int n = gp0 & (PN - 1);
        const float* fp = fea + (size_t)b * PC * PN + n;

        ull accA[32], accB[32];
        ull agA[4],  agB[4];
        #pragma unroll
        for (int i = 0; i < 32; i++) { accA[i] = lds64(aBv + i * 8); accB[i] = accA[i]; }
        #pragma unroll
        for (int i = 0; i < 4; i++)  { agA[i]  = lds64(aA0 + i * 8); agB[i] = agA[i]; }

        #pragma unroll 2
        for (int c = 0; c < 64; c++) {
            float2 f2 = *(const float2*)(fp + (size_t)c * PN);
            ull fA = pack2(f2.x, f2.x);
            ull fB = pack2(f2.y, f2.y);
            uint32_t rowa = aWv + c * 256;
            #pragma unroll
            for (int p = 0; p < 16; p++) {
                ull w0, w1;
                lds128(w0, w1, rowa + p * 16);
                ffma2(accA[p * 2 + 0], fA, w0, accA[p * 2 + 0]);
                ffma2(accA[p * 2 + 1], fA, w1, accA[p * 2 + 1]);
                ffma2(accB[p * 2 + 0], fB, w0, accB[p * 2 + 0]);
                ffma2(accB[p * 2 + 1], fB, w1, accB[p * 2 + 1]);
            }
            ull k0, k1, k2, k3;
            lds128(k0, k1, aKa + c * 32);
            lds128(k2, k3, aKa + c * 32 + 16);
            ffma2(agA[0], fA, k0, agA[0]);  ffma2(agA[1], fA, k1, agA[1]);
            ffma2(agA[2], fA, k2, agA[2]);  ffma2(agA[3], fA, k3, agA[3]);
            ffma2(agB[0], fB, k0, agB[0]);  ffma2(agB[1], fB, k1, agB[1]);
            ffma2(agB[2], fB, k2, agB[2]);  ffma2(agB[3], fB, k3, agB[3]);
        }

        float* ovA = g_xv + (size_t)gp0 * 64;
        float* ovB = ovA + 64;
        #pragma unroll
        for (int p = 0; p < 16; p++) {
            stg128(ovA + p * 4, accA[p * 2], accA[p * 2 + 1]);
            stg128(ovB + p * 4, accB[p * 2], accB[p * 2 + 1]);
        }
        float* avA = g_a + (size_t)gp0 * 8;
        stg128(avA,      agA[0], agA[1]);
        stg128(avA + 4,  agA[2], agA[3]);
        stg128(avA + 8,  agB[0], agB[1]);
        stg128(avA + 12, agB[2], agB[3]);
    } else {
        // ---------------- center path ----------------
        float* sWqa = su;            // 512
        float* sWca = su + 512;      // 512
        float* sw1  = su + 1024;     // 192
        float* sb1  = su + 1216;     // 64
        float* sc0  = su + 1280;     // 8
        // in-block fold: sWqa / sWca (each thread: 4+4 values)
        {
            int c  = tid >> 1;
            int g0 = (tid & 1) * 4;
            float4 aq = make_float4(0.f, 0.f, 0.f, 0.f);
            float4 ac = make_float4(0.f, 0.f, 0.f, 0.f);
            #pragma unroll 8
            for (int o = 0; o < 64; o++) {
                float wq = __ldg(Wq + c * 64 + o);
                float wc = __ldg(cpe_w2 + c * 64 + o);
                float4 ww = *(const float4*)(we_w1 + o * 8 + g0);
                aq.x = fmaf(wq, ww.x, aq.x); aq.y = fmaf(wq, ww.y, aq.y);
                aq.z = fmaf(wq, ww.z, aq.z); aq.w = fmaf(wq, ww.w, aq.w);
                ac.x = fmaf(wc, ww.x, ac.x); ac.y = fmaf(wc, ww.y, ac.y);
                ac.z = fmaf(wc, ww.z, ac.z); ac.w = fmaf(wc, ww.w, ac.w);
            }
            float4 ws = *(const float4*)(we_s + g0);
            sWqa[c * 8 + g0 + 0] = aq.x * ws.x;
            sWqa[c * 8 + g0 + 1] = aq.y * ws.y;
            sWqa[c * 8 + g0 + 2] = aq.z * ws.z;
            sWqa[c * 8 + g0 + 3] = aq.w * ws.w;
            sWca[c * 8 + g0 + 0] = ac.x * ws.x;
            sWca[c * 8 + g0 + 1] = ac.y * ws.y;
            sWca[c * 8 + g0 + 2] = ac.z * ws.z;
            sWca[c * 8 + g0 + 3] = ac.w * ws.w;
        }
        for (int i = tid; i < 192; i += 128) {
            int j = i % 64;
            sw1[i] = cpe_w1[i] * cpe_s[j];
        }
        if (tid < 64) sb1[tid] = cpe_b[tid];
        if (tid < 8) {
            float c0 = 0.f;
            #pragma unroll 8
            for (int o = 0; o < 64; o++)
                c0 = fmaf(__ldg(bq + o) - __ldg(cpe_b2 + o), we_w1[o * 8 + tid], c0);
            sc0[tid] = c0 * we_s[tid] - we_b[tid];
        }
        __syncthreads();

        int gid = (blockIdx.x - 256) * 128 + tid;
        float px = center_pos[(size_t)gid * 3 + 0];
        float py = center_pos[(size_t)gid * 3 + 1];
        float pz = center_pos[(size_t)gid * 3 + 2];

        float acc[8];
        #pragma unroll
        for (int g = 0; g < 8; g++) acc[g] = sc0[g];

        int b = gid >> 14;
        int m = gid & (PM - 1);
        const float* cf = center_fea + (size_t)b * PC * PM + m;
        #pragma unroll 4
        for (int i = 0; i < 64; i++) {
            float h = fmaxf(fmaf(px, sw1[i], fmaf(py, sw1[64 + i], fmaf(pz, sw1[128 + i], sb1[i]))), 0.f);
            float f = cf[(size_t)i * PM];
            const float4* qa = (const float4*)(sWqa + i * 8);
            const float4* ca = (const float4*)(sWca + i * 8);
            float4 q0 = qa[0], q1 = qa[1], c0 = ca[0], c1 = ca[1];
            acc[0] += f * q0.x - h * c0.x;  acc[1] += f * q0.y - h * c0.y;
            acc[2] += f * q0.z - h * c0.z;  acc[3] += f * q0.w - h * c0.w;
            acc[4] += f * q1.x - h * c1.x;  acc[5] += f * q1.y - h * c1.y;
            acc[6] += f * q1.z - h * c1.z;  acc[7] += f * q1.w - h * c1.w;
        }
        float4* cv = (float4*)(g_c + (size_t)gid * 8);
        cv[0] = make_float4(acc[0], acc[1], acc[2], acc[3]);
        cv[1] = make_float4(acc[4], acc[5], acc[6], acc[7]);
    }
}

// ---------------------------------------------------------------------------
// Kernel 3: main attention — identical to R12 except pe_w1*pe_s fold inlined
// (fold_kernel removed).
// ---------------------------------------------------------------------------
// smem float layout:
//   0     s_we2  [64]
//   64    s_web2 [8]
//   72    s_ikd  [8*16 float4] = 512
//   584   s_w    [8*16*16] = 2048      duplicated {w,w} pairs
//   2632  s_H    [8 * 576]             8 rows x 72 floats per center
#define SM_WE2   0
#define SM_WEB2  64
#define SM_IKD   72
#define SM_W     584
#define SM_H     2632
#define SM_TOT   (2632 + 8 * 576)

__global__ void __launch_bounds__(128, 5)
attn_kernel(const float* __restrict__ center_pos,
            const float* __restrict__ pos,
            const int* __restrict__ idx,
            const float* __restrict__ pe_w1,
            const float* __restrict__ pe_s,
            const float* __restrict__ pe_w2,
            const float* __restrict__ pe_b,
            const float* __restrict__ pe_b2,
            const float* __restrict__ we_w2,
            const float* __restrict__ we_b2,
            float* __restrict__ out) {
    extern __shared__ float sm[];
    float*  s_we2  = sm + SM_WE2;
    float*  s_web2 = sm + SM_WEB2;
    float4* s_ikd  = (float4*)(sm + SM_IKD);
    float4* s_w4   = (float4*)(sm + SM_W);
    float*  s_H    = sm + SM_H;

    const int tid = threadIdx.x;
    if (tid < 64) s_we2[tid] = we_w2[tid];
    if (tid < 8)  s_web2[tid] = we_b2[tid];
    __syncthreads();

    const unsigned FULL = 0xffffffffu;
    const int ci = tid >> 4;           // center within block (0..7)
    const int t  = tid & 15;           // lane within center
    const int g  = t >> 1;             // my output group
    const int gidBase = blockIdx.x * 8;
    const int gid = gidBase + ci;
    const int b = gid >> 14;

    const uint32_t aBase = (uint32_t)__cvta_generic_to_shared(sm);
    const uint32_t aW    = aBase + SM_W * 4 + ci * 1024;   // this center's w-pairs

    // --- prologue: my edge (k = t) ---
    int myik;
    {
        int ik = idx[(size_t)gid * 16 + t];
        myik = b * PN + ik;
        const float* pp = pos + (size_t)myik * 3;
        float cx = center_pos[(size_t)gid * 3 + 0];
        float cy = center_pos[(size_t)gid * 3 + 1];
        float cz = center_pos[(size_t)gid * 3 + 2];
        s_ikd[ci * 16 + t] = make_float4(pp[0] - cx, pp[1] - cy, pp[2] - cz,
                                         __int_as_float(myik));
    }

    // --- logits + softmax for my edge ---
    {
        const float4* cpv = (const float4*)(g_c + (size_t)gid * 8);
        float4 cA = cpv[0], cB = cpv[1];
        const float4* ap = (const float4*)(g_a + (size_t)myik * 8);
        float4 a0 = ap[0], a1 = ap[1];
        float h1[8];
        h1[0] = fmaxf(a0.x - cA.x, 0.f); h1[1] = fmaxf(a0.y - cA.y, 0.f);
        h1[2] = fmaxf(a0.z - cA.z, 0.f); h1[3] = fmaxf(a0.w - cA.w, 0.f);
        h1[4] = fmaxf(a1.x - cB.x, 0.f); h1[5] = fmaxf(a1.y - cB.y, 0.f);
        h1[6] = fmaxf(a1.z - cB.z, 0.f); h1[7] = fmaxf(a1.w - cB.w, 0.f);

        float4 b0 = *(const float4*)(s_web2);
        float4 b1 = *(const float4*)(s_web2 + 4);
        float lg[8] = {b0.x, b0.y, b0.z, b0.w, b1.x, b1.y, b1.z, b1.w};
        #pragma unroll
        for (int gp = 0; gp < 8; gp++) {
            float hv = h1[gp];
            float4 wa = *(const float4*)(s_we2 + gp * 8);
            float4 wb = *(const float4*)(s_we2 + gp * 8 + 4);
            lg[0] = fmaf(hv, wa.x, lg[0]); lg[1] = fmaf(hv, wa.y, lg[1]);
            lg[2] = fmaf(hv, wa.z, lg[2]); lg[3] = fmaf(hv, wa.w, lg[3]);
            lg[4] = fmaf(hv, wb.x, lg[4]); lg[5] = fmaf(hv, wb.y, lg[5]);
            lg[6] = fmaf(hv, wb.z, lg[6]); lg[7] = fmaf(hv, wb.w, lg[7]);
        }
        float mx[8];
        #pragma unroll
        for (int gg = 0; gg < 8; gg++) mx[gg] = lg[gg];
        #pragma unroll
        for (int s = 1; s < 16; s <<= 1)
            #pragma unroll
            for (int gg = 0; gg < 8; gg++)
                mx[gg] = fmaxf(mx[gg], __shfl_xor_sync(FULL, mx[gg], s, 16));
        float e[8], sum[8];
        #pragma unroll
        for (int gg = 0; gg < 8; gg++) { e[gg] = __expf(lg[gg] - mx[gg]); sum[gg] = e[gg]; }
        #pragma unroll
        for (int s = 1; s < 16; s <<= 1)
            #pragma unroll
            for (int gg = 0; gg < 8; gg++)
                sum[gg] += __shfl_xor_sync(FULL, sum[gg], s, 16);
        #pragma unroll
        for (int gg = 0; gg < 8; gg++)
            e[gg] *= __fdividef(1.f, sum[gg]);
        float4* wb4 = s_w4 + (ci * 16 + t) * 4;
        wb4[0] = make_float4(e[0], e[0], e[1], e[1]);
        wb4[1] = make_float4(e[2], e[2], e[3], e[3]);
        wb4[2] = make_float4(e[4], e[4], e[5], e[5]);
        wb4[3] = make_float4(e[6], e[6], e[7], e[7]);
    }
    __syncwarp();

    // --- per-thread pe_w1 slice (folded with pe_s inline) + bias ---
    float wxa[4], wxb[4], wxc[4], bb[4];
    #pragma unroll
    for (int jj = 0; jj < 4; jj++) {
        float ps = __ldg(pe_s + t * 4 + jj);
        wxa[jj] = __ldg(pe_w1 + 0 * 64 + t * 4 + jj) * ps;
        wxb[jj] = __ldg(pe_w1 + 1 * 64 + t * 4 + jj) * ps;
        wxc[jj] = __ldg(pe_w1 + 2 * 64 + t * 4 + jj) * ps;
        bb[jj]  = __ldg(pe_b + t * 4 + jj);
    }

    // --- edge loop (R9 structure) ---
    ull Hc2[16];           // Hc2[gg*2+p] = {H[gg][j-pair p]}
    ull onv2[2] = {0ull, 0ull};
    #pragma unroll
    for (int i = 0; i < 16; i++) Hc2[i] = 0ull;

    #pragma unroll
    for (int k = 0; k < 16; k++) {
        float4 d = *(float4*)((char*)sm + (SM_IKD * 4 + ci * 256 + k * 16));
        int ikk = __float_as_int(d.w);
        ull wp0, wp1, wp2, wp3, wp4, wp5, wp6, wp7;
        lds128(wp0, wp1, aW + k * 64);
        lds128(wp2, wp3, aW + k * 64 + 16);
        lds128(wp4, wp5, aW + k * 64 + 32);
        lds128(wp6, wp7, aW + k * 64 + 48);
        ull wtp = lds64(aW + k * 64 + g * 8);
        ull v0, v1;
        ldg128(v0, v1, g_xv + (size_t)ikk * 64 + t * 4);

        float h0 = fmaxf(fmaf(d.x, wxa[0], fmaf(d.y, wxb[0], fmaf(d.z, wxc[0], bb[0]))), 0.f);
        float h1 = fmaxf(fmaf(d.x, wxa[1], fmaf(d.y, wxb[1], fmaf(d.z, wxc[1], bb[1]))), 0.f);
        float h2 = fmaxf(fmaf(d.x, wxa[2], fmaf(d.y, wxb[2], fmaf(d.z, wxc[2], bb[2]))), 0.f);
        float h3 = fmaxf(fmaf(d.x, wxa[3], fmaf(d.y, wxb[3], fmaf(d.z, wxc[3], bb[3]))), 0.f);
        ull h01 = pack2(h0, h1);
        ull h23 = pack2(h2, h3);

        ffma2(Hc2[0],  wp0, h01, Hc2[0]);  ffma2(Hc2[1],  wp0, h23, Hc2[1]);
        ffma2(Hc2[2],  wp1, h01, Hc2[2]);  ffma2(Hc2[3],  wp1, h23, Hc2[3]);
        ffma2(Hc2[4],  wp2, h01, Hc2[4]);  ffma2(Hc2[5],  wp2, h23, Hc2[5]);
        ffma2(Hc2[6],  wp3, h01, Hc2[6]);  ffma2(Hc2[7],  wp3, h23, Hc2[7]);
        ffma2(Hc2[8],  wp4, h01, Hc2[8]);  ffma2(Hc2[9],  wp4, h23, Hc2[9]);
        ffma2(Hc2[10], wp5, h01, Hc2[10]); ffma2(Hc2[11], wp5, h23, Hc2[11]);
        ffma2(Hc2[12], wp6, h01, Hc2[12]); ffma2(Hc2[13], wp6, h23, Hc2[13]);
        ffma2(Hc2[14], wp7, h01, Hc2[14]); ffma2(Hc2[15], wp7, h23, Hc2[15]);

        ffma2(onv2[0], wtp, v0, onv2[0]);
        ffma2(onv2[1], wtp, v1, onv2[1]);
    }

    // --- H transpose through smem (warp-local) ---
    {
        uint32_t aH = aBase + SM_H * 4 + ci * 2304 + t * 16;
        #pragma unroll
        for (int gg = 0; gg < 8; gg++)
            sts128(aH + gg * 288, Hc2[gg * 2], Hc2[gg * 2 + 1]);
    }
    __syncwarp();

    // --- j-split epilogue: half-warp h covers j in [32h, 32h+32) for BOTH of
    //     its warp's centers; exchange partials via shfl_xor(16). ---
    const int wnum = tid >> 5;
    const int h    = (tid >> 4) & 1;
    const int jb   = h * 32;
    ull pA0 = 0, pA1 = 0, pB0 = 0, pB1 = 0;
    {
        const float* hr0 = s_H + (wnum * 2 + 0) * 576 + g * 72 + jb;
        const float* hr1 = s_H + (wnum * 2 + 1) * 576 + g * 72 + jb;
        const float* pwb = pe_w2 + t * 4 + jb * 64;
        #pragma unroll 4
        for (int j4 = 0; j4 < 8; j4++) {
            float4 hA = *(const float4*)(hr0 + j4 * 4);
            float4 hB = *(const float4*)(hr1 + j4 * 4);
            ull p0, p1, hp;
            ldg128(p0, p1, pwb + (j4 * 4 + 0) * 64);
            hp = pack2(hA.x, hA.x); ffma2(pA0, hp, p0, pA0); ffma2(pA1, hp, p1, pA1);
            hp = pack2(hB.x, hB.x); ffma2(pB0, hp, p0, pB0); ffma2(pB1, hp, p1, pB1);
            ldg128(p0, p1, pwb + (j4 * 4 + 1) * 64);
            hp = pack2(hA.y, hA.y); ffma2(pA0, hp, p0, pA0); ffma2(pA1, hp, p1, pA1);
            hp = pack2(hB.y, hB.y); ffma2(pB0, hp, p0, pB0); ffma2(pB1, hp, p1, pB1);
            ldg128(p0, p1, pwb + (j4 * 4 + 2) * 64);
            hp = pack2(hA.z, hA.z); ffma2(pA0, hp, p0, pA0); ffma2(pA1, hp, p1, pA1);
            hp = pack2(hB.z, hB.z); ffma2(pB0, hp, p0, pB0); ffma2(pB1, hp, p1, pB1);
            ldg128(p0, p1, pwb + (j4 * 4 + 3) * 64);
            hp = pack2(hA.w, hA.w); ffma2(pA0, hp, p0, pA0); ffma2(pA1, hp, p1, pA1);
            hp = pack2(hB.w, hB.w); ffma2(pB0, hp, p0, pB0); ffma2(pB1, hp, p1, pB1);
        }
    }
    ull own0 = h ? pB0 : pA0, own1 = h ? pB1 : pA1;
    ull oth0 = h ? pA0 : pB0, oth1 = h ? pA1 : pB1;
    ull r0 = __shfl_xor_sync(FULL, oth0, 16);
    ull r1 = __shfl_xor_sync(FULL, oth1, 16);
    ull pr0, pr1;
    fadd2(pr0, own0, r0);
    fadd2(pr1, own1, r1);
    fadd2(pr0, pr0, pack2(__ldg(pe_b2 + t * 4 + 0), __ldg(pe_b2 + t * 4 + 1)));
    fadd2(pr1, pr1, pack2(__ldg(pe_b2 + t * 4 + 2), __ldg(pe_b2 + t * 4 + 3)));
    __syncthreads();   // all warps done with s_H — safe to overlay s_out

    // --- stage output [o][m_local] for coalesced [B,O,M] writes ---
    float* s_out = s_H;   // 64 x 9 overlay
    {
        float2 a0 = unpack2(onv2[0]), a1 = unpack2(onv2[1]);
        float2 q0 = unpack2(pr0),     q1 = unpack2(pr1);
        s_out[(t * 4 + 0) * 9 + ci] = a0.x + q0.x;
        s_out[(t * 4 + 1) * 9 + ci] = a0.y + q0.y;
        s_out[(t * 4 + 2) * 9 + ci] = a1.x + q1.x;
        s_out[(t * 4 + 3) * 9 + ci] = a1.y + q1.y;
    }
    __syncthreads();

    const int m0 = gidBase & (PM - 1);
    float* ob = out + (size_t)(gidBase >> 14) * PO * PM + m0;
    #pragma unroll
    for (int q = 0; q < 4; q++) {
        int lin = q * 128 + tid;
        int o = lin >> 3;
        int ml = lin & 7;
        ob[(size_t)o * PM + ml] = s_out[o * 9 + ml];
    }
}

// ---------------------------------------------------------------------------
extern "C" void kernel_launch(void* const* d_in, const int* in_sizes, int n_in,
                              void* d_out, int out_size) {
    (void)in_sizes; (void)n_in; (void)out_size;
    const float* center_pos = (const float*)d_in[0];
    const float* center_fea = (const float*)d_in[1];
    const float* pos        = (const float*)d_in[2];
    const float* fea        = (const float*)d_in[3];
    const int*   idx        = (const int*)d_in[4];
    const float* Wq  = (const float*)d_in[5];
    const float* bq  = (const float*)d_in[6];
    const float* Wk  = (const float*)d_in[7];
    const float* bk  = (const float*)d_in[8];
    const float* Wv  = (const float*)d_in[9];
    const float* bv  = (const float*)d_in[10];
    const float* cpe_w1 = (const float*)d_in[11];
    const float* cpe_s  = (const float*)d_in[12];
    const float* cpe_b  = (const float*)d_in[13];
    const float* cpe_w2 = (const float*)d_in[14];
    const float* cpe_b2 = (const float*)d_in[15];
    const float* pe_w1  = (const float*)d_in[16];
    const float* pe_s   = (const float*)d_in[17];
    const float* pe_b   = (const float*)d_in[18];
    const float* pe_w2  = (const float*)d_in[19];
    const float* pe_b2  = (const float*)d_in[20];
    const float* we_w1  = (const float*)d_in[21];
    const float* we_s   = (const float*)d_in[22];
    const float* we_b   = (const float*)d_in[23];
    const float* we_w2  = (const float*)d_in[24];
    const float* we_b2  = (const float*)d_in[25];
    float* out = (float*)d_out;

    pc_kernel<<<768, 128>>>(fea, Wv, bv, Wq, bq, Wk, bk,
                            cpe_w1, cpe_s, cpe_b, cpe_w2, cpe_b2,
                            we_w1, we_s, we_b, center_pos, center_fea);

    const int smem = SM_TOT * 4;   // ~28.3 KB
    cudaFuncSetAttribute(attn_kernel, cudaFuncAttributeMaxDynamicSharedMemorySize, smem);
    attn_kernel<<<(PB * PM) / 8, 128, smem>>>(center_pos, pos, idx,
                                              pe_w1, pe_s, pe_w2, pe_b, pe_b2,
                                              we_w2, we_b2, out);
}

// round 15
// speedup vs baseline: 1.1279x; 1.1279x over previous
#include <cuda_runtime.h>
#include <cstddef>
#include <cstdint>

// Problem constants
#define PB 4
#define PN 16384
#define PM 16384
#define PK 16
#define PC 64
#define PO 64
#define PG 8

typedef unsigned long long ull;

// ---- f32x2 packed helpers (sm_103a FFMA2 path) ----
__device__ __forceinline__ void ffma2(ull& d, ull a, ull b, ull c) {
    asm("fma.rn.f32x2 %0, %1, %2, %3;" : "=l"(d) : "l"(a), "l"(b), "l"(c));
}
__device__ __forceinline__ void fadd2(ull& d, ull a, ull b) {
    asm("add.rn.f32x2 %0, %1, %2;" : "=l"(d) : "l"(a), "l"(b));
}
__device__ __forceinline__ ull pack2(float lo, float hi) {
    ull r; asm("mov.b64 %0, {%1, %2};" : "=l"(r) : "f"(lo), "f"(hi)); return r;
}
__device__ __forceinline__ float2 unpack2(ull v) {
    float2 f; asm("mov.b64 {%0, %1}, %2;" : "=f"(f.x), "=f"(f.y) : "l"(v)); return f;
}
__device__ __forceinline__ ull lds64(uint32_t a) {
    ull r; asm volatile("ld.shared.b64 %0, [%1];" : "=l"(r) : "r"(a)); return r;
}
__device__ __forceinline__ void lds128(ull& x, ull& y, uint32_t a) {
    asm volatile("ld.shared.v2.b64 {%0,%1}, [%2];" : "=l"(x), "=l"(y) : "r"(a));
}
__device__ __forceinline__ void sts128(uint32_t a, ull x, ull y) {
    asm volatile("st.shared.v2.b64 [%0], {%1,%2};" :: "r"(a), "l"(x), "l"(y) : "memory");
}
__device__ __forceinline__ void ldg128(ull& x, ull& y, const void* p) {
    asm volatile("ld.global.nc.v2.b64 {%0,%1}, [%2];" : "=l"(x), "=l"(y) : "l"(p));
}
__device__ __forceinline__ void stg128(void* p, ull x, ull y) {
    asm volatile("st.global.v2.b64 [%0], {%1,%2};" :: "l"(p), "l"(x), "l"(y) : "memory");
}

static __device__ float g_xv[PB * PN * PO];   // x_v [B,N,64]
static __device__ float g_a [PB * PN * PG];   // per-point logit precursor [B,N,8]
static __device__ float g_c [PB * PM * PG];   // per-center logit precursor [B,M,8]

// ---------------------------------------------------------------------------
// Kernel 1+2 merged; weight folds recomputed in-block from COALESCED smem
// staging (R14's direct-gmem fold doubled L1 wavefronts — fixed here).
// blocks [0,256): per-point precompute (2 pts/thread)
// blocks [256,768): per-center precompute (1 center/thread)
// ---------------------------------------------------------------------------
__global__ void __launch_bounds__(128, 2)
pc_kernel(const float* __restrict__ fea,
          const float* __restrict__ Wv,
          const float* __restrict__ bv,
          const float* __restrict__ Wq, const float* __restrict__ bq,
          const float* __restrict__ Wk, const float* __restrict__ bk,
          const float* __restrict__ cpe_w1, const float* __restrict__ cpe_s,
          const float* __restrict__ cpe_b,
          const float* __restrict__ cpe_w2, const float* __restrict__ cpe_b2,
          const float* __restrict__ we_w1, const float* __restrict__ we_s,
          const float* __restrict__ we_b,
          const float* __restrict__ center_pos,
          const float* __restrict__ center_fea) {
    __shared__ float su[10504];    // 42 KB: max(point 9544, center 10504)
    int tid = threadIdx.x;

    if (blockIdx.x < 256) {
        // ---------------- point path ----------------
        float* sWv  = su;            // 4096
        float* sWka = su + 4096;     // 512
        float* sbv  = su + 4608;     // 64
        float* sa0  = su + 4672;     // 8
        float* sWW  = su + 4680;     // 512 (we_w1)
        float* sWk  = su + 5192;     // 64 rows x stride 68 = 4352
        for (int i = tid; i < 4096; i += 128) sWv[i] = Wv[i];
        for (int i = tid; i < 4096; i += 128) {
            int c = i >> 6, o = i & 63;
            sWk[c * 68 + o] = Wk[i];
        }
        *(float4*)(sWW + tid * 4) = *(const float4*)(we_w1 + tid * 4);
        if (tid < 64) sbv[tid] = bv[tid];
        __syncthreads();

        uint32_t aWW = (uint32_t)__cvta_generic_to_shared(sWW);

        // fold from smem: sWka[c*8+g] = (Wk[c,:]·we_w1[:,g]) * we_s[g]
        {
            int c  = tid >> 1;
            int g0 = (tid & 1) * 4;
            ull acc01 = 0ull, acc23 = 0ull;
            #pragma unroll 8
            for (int o = 0; o < 64; o++) {
                float w = sWk[c * 68 + o];
                ull w01, w23;
                lds128(w01, w23, aWW + o * 32 + g0 * 4);
                ull hp = pack2(w, w);
                ffma2(acc01, hp, w01, acc01);
                ffma2(acc23, hp, w23, acc23);
            }
            float2 a01 = unpack2(acc01), a23 = unpack2(acc23);
            sWka[c * 8 + g0 + 0] = a01.x * __ldg(we_s + g0 + 0);
            sWka[c * 8 + g0 + 1] = a01.y * __ldg(we_s + g0 + 1);
            sWka[c * 8 + g0 + 2] = a23.x * __ldg(we_s + g0 + 2);
            sWka[c * 8 + g0 + 3] = a23.y * __ldg(we_s + g0 + 3);
        }
        if (tid < 8) {
            float a0 = 0.f;
            #pragma unroll 8
            for (int o = 0; o < 64; o++)
                a0 = fmaf(__ldg(bk + o), sWW[o * 8 + tid], a0);
            sa0[tid] = a0 * __ldg(we_s + tid);
        }
        __syncthreads();

        uint32_t aWv = (uint32_t)__cvta_generic_to_shared(sWv);
        uint32_t aKa = (uint32_t)__cvta_generic_to_shared(sWka);
        uint32_t aBv = (uint32_t)__cvta_generic_to_shared(sbv);
        uint32_t aA0 = (uint32_t)__cvta_generic_to_shared(sa0);

        int gp0 = (blockIdx.x * 128 + tid) * 2;   // two adjacent points
        int b = gp0 >> 14;
        int n = gp0 & (PN - 1);
        const float* fp = fea + (size_t)b * PC * PN + n;

        ull accA[32], accB[32];
        ull agA[4],  agB[4];
        #pragma unroll
        for (int i = 0; i < 32; i++) { accA[i] = lds64(aBv + i * 8); accB[i] = accA[i]; }
        #pragma unroll
        for (int i = 0; i < 4; i++)  { agA[i]  = lds64(aA0 + i * 8); agB[i] = agA[i]; }

        #pragma unroll 2
        for (int c = 0; c < 64; c++) {
            float2 f2 = *(const float2*)(fp + (size_t)c * PN);
            ull fA = pack2(f2.x, f2.x);
            ull fB = pack2(f2.y, f2.y);
            uint32_t rowa = aWv + c * 256;
            #pragma unroll
            for (int p = 0; p < 16; p++) {
                ull w0, w1;
                lds128(w0, w1, rowa + p * 16);
                ffma2(accA[p * 2 + 0], fA, w0, accA[p * 2 + 0]);
                ffma2(accA[p * 2 + 1], fA, w1, accA[p * 2 + 1]);
                ffma2(accB[p * 2 + 0], fB, w0, accB[p * 2 + 0]);
                ffma2(accB[p * 2 + 1], fB, w1, accB[p * 2 + 1]);
            }
            ull k0, k1, k2, k3;
            lds128(k0, k1, aKa + c * 32);
            lds128(k2, k3, aKa + c * 32 + 16);
            ffma2(agA[0], fA, k0, agA[0]);  ffma2(agA[1], fA, k1, agA[1]);
            ffma2(agA[2], fA, k2, agA[2]);  ffma2(agA[3], fA, k3, agA[3]);
            ffma2(agB[0], fB, k0, agB[0]);  ffma2(agB[1], fB, k1, agB[1]);
            ffma2(agB[2], fB, k2, agB[2]);  ffma2(agB[3], fB, k3, agB[3]);
        }

        float* ovA = g_xv + (size_t)gp0 * 64;
        float* ovB = ovA + 64;
        #pragma unroll
        for (int p = 0; p < 16; p++) {
            stg128(ovA + p * 4, accA[p * 2], accA[p * 2 + 1]);
            stg128(ovB + p * 4, accB[p * 2], accB[p * 2 + 1]);
        }
        float* avA = g_a + (size_t)gp0 * 8;
        stg128(avA,      agA[0], agA[1]);
        stg128(avA + 4,  agA[2], agA[3]);
        stg128(avA + 8,  agB[0], agB[1]);
        stg128(avA + 12, agB[2], agB[3]);
    } else {
        // ---------------- center path ----------------
        float* sWqa = su;            // 512
        float* sWca = su + 512;      // 512
        float* sw1  = su + 1024;     // 192
        float* sb1  = su + 1216;     // 64
        float* sc0  = su + 1280;     // 8
        float* sWW  = su + 1288;     // 512
        float* sWq  = su + 1800;     // 4352 (stride 68)
        float* sWc  = su + 6152;     // 4352 (stride 68)
        for (int i = tid; i < 4096; i += 128) {
            int c = i >> 6, o = i & 63;
            sWq[c * 68 + o] = Wq[i];
            sWc[c * 68 + o] = cpe_w2[i];
        }
        *(float4*)(sWW + tid * 4) = *(const float4*)(we_w1 + tid * 4);
        for (int i = tid; i < 192; i += 128) {
            int j = i % 64;
            sw1[i] = cpe_w1[i] * cpe_s[j];
        }
        if (tid < 64) sb1[tid] = cpe_b[tid];
        __syncthreads();

        uint32_t aWW = (uint32_t)__cvta_generic_to_shared(sWW);

        // fold both Wq and cpe_w2 against we_w1 (smem-resident, coalesced)
        {
            int c  = tid >> 1;
            int g0 = (tid & 1) * 4;
            ull aq01 = 0ull, aq23 = 0ull, ac01 = 0ull, ac23 = 0ull;
            #pragma unroll 8
            for (int o = 0; o < 64; o++) {
                float wq = sWq[c * 68 + o];
                float wc = sWc[c * 68 + o];
                ull w01, w23;
                lds128(w01, w23, aWW + o * 32 + g0 * 4);
                ull hq = pack2(wq, wq);
                ull hc = pack2(wc, wc);
                ffma2(aq01, hq, w01, aq01);
                ffma2(aq23, hq, w23, aq23);
                ffma2(ac01, hc, w01, ac01);
                ffma2(ac23, hc, w23, ac23);
            }
            float2 q01 = unpack2(aq01), q23 = unpack2(aq23);
            float2 c01 = unpack2(ac01), c23 = unpack2(ac23);
            float s0 = __ldg(we_s + g0 + 0), s1 = __ldg(we_s + g0 + 1);
            float s2 = __ldg(we_s + g0 + 2), s3 = __ldg(we_s + g0 + 3);
            sWqa[c * 8 + g0 + 0] = q01.x * s0;
            sWqa[c * 8 + g0 + 1] = q01.y * s1;
            sWqa[c * 8 + g0 + 2] = q23.x * s2;
            sWqa[c * 8 + g0 + 3] = q23.y * s3;
            sWca[c * 8 + g0 + 0] = c01.x * s0;
            sWca[c * 8 + g0 + 1] = c01.y * s1;
            sWca[c * 8 + g0 + 2] = c23.x * s2;
            sWca[c * 8 + g0 + 3] = c23.y * s3;
        }
        if (tid < 8) {
            float c0 = 0.f;
            #pragma unroll 8
            for (int o = 0; o < 64; o++)
                c0 = fmaf(__ldg(bq + o) - __ldg(cpe_b2 + o), sWW[o * 8 + tid], c0);
            sc0[tid] = c0 * __ldg(we_s + tid) - __ldg(we_b + tid);
        }
        __syncthreads();

        int gid = (blockIdx.x - 256) * 128 + tid;
        float px = center_pos[(size_t)gid * 3 + 0];
        float py = center_pos[(size_t)gid * 3 + 1];
        float pz = center_pos[(size_t)gid * 3 + 2];

        float acc[8];
        #pragma unroll
        for (int g = 0; g < 8; g++) acc[g] = sc0[g];

        int b = gid >> 14;
        int m = gid & (PM - 1);
        const float* cf = center_fea + (size_t)b * PC * PM + m;
        #pragma unroll 4
        for (int i = 0; i < 64; i++) {
            float h = fmaxf(fmaf(px, sw1[i], fmaf(py, sw1[64 + i], fmaf(pz, sw1[128 + i], sb1[i]))), 0.f);
            float f = cf[(size_t)i * PM];
            const float4* qa = (const float4*)(sWqa + i * 8);
            const float4* ca = (const float4*)(sWca + i * 8);
            float4 q0 = qa[0], q1 = qa[1], c0 = ca[0], c1 = ca[1];
            acc[0] += f * q0.x - h * c0.x;  acc[1] += f * q0.y - h * c0.y;
            acc[2] += f * q0.z - h * c0.z;  acc[3] += f * q0.w - h * c0.w;
            acc[4] += f * q1.x - h * c1.x;  acc[5] += f * q1.y - h * c1.y;
            acc[6] += f * q1.z - h * c1.z;  acc[7] += f * q1.w - h * c1.w;
        }
        float4* cv = (float4*)(g_c + (size_t)gid * 8);
        cv[0] = make_float4(acc[0], acc[1], acc[2], acc[3]);
        cv[1] = make_float4(acc[4], acc[5], acc[6], acc[7]);
    }
}

// ---------------------------------------------------------------------------
// Kernel 3: main attention — identical to R14 (101.8us, best).
// ---------------------------------------------------------------------------
// smem float layout:
//   0     s_we2  [64]
//   64    s_web2 [8]
//   72    s_ikd  [8*16 float4] = 512
//   584   s_w    [8*16*16] = 2048      duplicated {w,w} pairs
//   2632  s_H    [8 * 576]             8 rows x 72 floats per center
#define SM_WE2   0
#define SM_WEB2  64
#define SM_IKD   72
#define SM_W     584
#define SM_H     2632
#define SM_TOT   (2632 + 8 * 576)

__global__ void __launch_bounds__(128, 5)
attn_kernel(const float* __restrict__ center_pos,
            const float* __restrict__ pos,
            const int* __restrict__ idx,
            const float* __restrict__ pe_w1,
            const float* __restrict__ pe_s,
            const float* __restrict__ pe_w2,
            const float* __restrict__ pe_b,
            const float* __restrict__ pe_b2,
            const float* __restrict__ we_w2,
            const float* __restrict__ we_b2,
            float* __restrict__ out) {
    extern __shared__ float sm[];
    float*  s_we2  = sm + SM_WE2;
    float*  s_web2 = sm + SM_WEB2;
    float4* s_ikd  = (float4*)(sm + SM_IKD);
    float4* s_w4   = (float4*)(sm + SM_W);
    float*  s_H    = sm + SM_H;

    const int tid = threadIdx.x;
    if (tid < 64) s_we2[tid] = we_w2[tid];
    if (tid < 8)  s_web2[tid] = we_b2[tid];
    __syncthreads();

    const unsigned FULL = 0xffffffffu;
    const int ci = tid >> 4;           // center within block (0..7)
    const int t  = tid & 15;           // lane within center
    const int g  = t >> 1;             // my output group
    const int gidBase = blockIdx.x * 8;
    const int gid = gidBase + ci;
    const int b = gid >> 14;

    const uint32_t aBase = (uint32_t)__cvta_generic_to_shared(sm);
    const uint32_t aW    = aBase + SM_W * 4 + ci * 1024;   // this center's w-pairs

    // --- prologue: my edge (k = t) ---
    int myik;
    {
        int ik = idx[(size_t)gid * 16 + t];
        myik = b * PN + ik;
        const float* pp = pos + (size_t)myik * 3;
        float cx = center_pos[(size_t)gid * 3 + 0];
        float cy = center_pos[(size_t)gid * 3 + 1];
        float cz = center_pos[(size_t)gid * 3 + 2];
        s_ikd[ci * 16 + t] = make_float4(pp[0] - cx, pp[1] - cy, pp[2] - cz,
                                         __int_as_float(myik));
    }

    // --- logits + softmax for my edge ---
    {
        const float4* cpv = (const float4*)(g_c + (size_t)gid * 8);
        float4 cA = cpv[0], cB = cpv[1];
        const float4* ap = (const float4*)(g_a + (size_t)myik * 8);
        float4 a0 = ap[0], a1 = ap[1];
        float h1[8];
        h1[0] = fmaxf(a0.x - cA.x, 0.f); h1[1] = fmaxf(a0.y - cA.y, 0.f);
        h1[2] = fmaxf(a0.z - cA.z, 0.f); h1[3] = fmaxf(a0.w - cA.w, 0.f);
        h1[4] = fmaxf(a1.x - cB.x, 0.f); h1[5] = fmaxf(a1.y - cB.y, 0.f);
        h1[6] = fmaxf(a1.z - cB.z, 0.f); h1[7] = fmaxf(a1.w - cB.w, 0.f);

        float4 b0 = *(const float4*)(s_web2);
        float4 b1 = *(const float4*)(s_web2 + 4);
        float lg[8] = {b0.x, b0.y, b0.z, b0.w, b1.x, b1.y, b1.z, b1.w};
        #pragma unroll
        for (int gp = 0; gp < 8; gp++) {
            float hv = h1[gp];
            float4 wa = *(const float4*)(s_we2 + gp * 8);
            float4 wb = *(const float4*)(s_we2 + gp * 8 + 4);
            lg[0] = fmaf(hv, wa.x, lg[0]); lg[1] = fmaf(hv, wa.y, lg[1]);
            lg[2] = fmaf(hv, wa.z, lg[2]); lg[3] = fmaf(hv, wa.w, lg[3]);
            lg[4] = fmaf(hv, wb.x, lg[4]); lg[5] = fmaf(hv, wb.y, lg[5]);
            lg[6] = fmaf(hv, wb.z, lg[6]); lg[7] = fmaf(hv, wb.w, lg[7]);
        }
        float mx[8];
        #pragma unroll
        for (int gg = 0; gg < 8; gg++) mx[gg] = lg[gg];
        #pragma unroll
        for (int s = 1; s < 16; s <<= 1)
            #pragma unroll
            for (int gg = 0; gg < 8; gg++)
                mx[gg] = fmaxf(mx[gg], __shfl_xor_sync(FULL, mx[gg], s, 16));
        float e[8], sum[8];
        #pragma unroll
        for (int gg = 0; gg < 8; gg++) { e[gg] = __expf(lg[gg] - mx[gg]); sum[gg] = e[gg]; }
        #pragma unroll
        for (int s = 1; s < 16; s <<= 1)
            #pragma unroll
            for (int gg = 0; gg < 8; gg++)
                sum[gg] += __shfl_xor_sync(FULL, sum[gg], s, 16);
        #pragma unroll
        for (int gg = 0; gg < 8; gg++)
            e[gg] *= __fdividef(1.f, sum[gg]);
        float4* wb4 = s_w4 + (ci * 16 + t) * 4;
        wb4[0] = make_float4(e[0], e[0], e[1], e[1]);
        wb4[1] = make_float4(e[2], e[2], e[3], e[3]);
        wb4[2] = make_float4(e[4], e[4], e[5], e[5]);
        wb4[3] = make_float4(e[6], e[6], e[7], e[7]);
    }
    __syncwarp();

    // --- per-thread pe_w1 slice (folded with pe_s inline) + bias ---
    float wxa[4], wxb[4], wxc[4], bb[4];
    #pragma unroll
    for (int jj = 0; jj < 4; jj++) {
        float ps = __ldg(pe_s + t * 4 + jj);
        wxa[jj] = __ldg(pe_w1 + 0 * 64 + t * 4 + jj) * ps;
        wxb[jj] = __ldg(pe_w1 + 1 * 64 + t * 4 + jj) * ps;
        wxc[jj] = __ldg(pe_w1 + 2 * 64 + t * 4 + jj) * ps;
        bb[jj]  = __ldg(pe_b + t * 4 + jj);
    }

    // --- edge loop (R9 structure) ---
    ull Hc2[16];           // Hc2[gg*2+p] = {H[gg][j-pair p]}
    ull onv2[2] = {0ull, 0ull};
    #pragma unroll
    for (int i = 0; i < 16; i++) Hc2[i] = 0ull;

    #pragma unroll
    for (int k = 0; k < 16; k++) {
        float4 d = *(float4*)((char*)sm + (SM_IKD * 4 + ci * 256 + k * 16));
        int ikk = __float_as_int(d.w);
        ull wp0, wp1, wp2, wp3, wp4, wp5, wp6, wp7;
        lds128(wp0, wp1, aW + k * 64);
        lds128(wp2, wp3, aW + k * 64 + 16);
        lds128(wp4, wp5, aW + k * 64 + 32);
        lds128(wp6, wp7, aW + k * 64 + 48);
        ull wtp = lds64(aW + k * 64 + g * 8);
        ull v0, v1;
        ldg128(v0, v1, g_xv + (size_t)ikk * 64 + t * 4);

        float h0 = fmaxf(fmaf(d.x, wxa[0], fmaf(d.y, wxb[0], fmaf(d.z, wxc[0], bb[0]))), 0.f);
        float h1 = fmaxf(fmaf(d.x, wxa[1], fmaf(d.y, wxb[1], fmaf(d.z, wxc[1], bb[1]))), 0.f);
        float h2 = fmaxf(fmaf(d.x, wxa[2], fmaf(d.y, wxb[2], fmaf(d.z, wxc[2], bb[2]))), 0.f);
        float h3 = fmaxf(fmaf(d.x, wxa[3], fmaf(d.y, wxb[3], fmaf(d.z, wxc[3], bb[3]))), 0.f);
        ull h01 = pack2(h0, h1);
        ull h23 = pack2(h2, h3);

        ffma2(Hc2[0],  wp0, h01, Hc2[0]);  ffma2(Hc2[1],  wp0, h23, Hc2[1]);
        ffma2(Hc2[2],  wp1, h01, Hc2[2]);  ffma2(Hc2[3],  wp1, h23, Hc2[3]);
        ffma2(Hc2[4],  wp2, h01, Hc2[4]);  ffma2(Hc2[5],  wp2, h23, Hc2[5]);
        ffma2(Hc2[6],  wp3, h01, Hc2[6]);  ffma2(Hc2[7],  wp3, h23, Hc2[7]);
        ffma2(Hc2[8],  wp4, h01, Hc2[8]);  ffma2(Hc2[9],  wp4, h23, Hc2[9]);
        ffma2(Hc2[10], wp5, h01, Hc2[10]); ffma2(Hc2[11], wp5, h23, Hc2[11]);
        ffma2(Hc2[12], wp6, h01, Hc2[12]); ffma2(Hc2[13], wp6, h23, Hc2[13]);
        ffma2(Hc2[14], wp7, h01, Hc2[14]); ffma2(Hc2[15], wp7, h23, Hc2[15]);

        ffma2(onv2[0], wtp, v0, onv2[0]);
        ffma2(onv2[1], wtp, v1, onv2[1]);
    }

    // --- H transpose through smem (warp-local) ---
    {
        uint32_t aH = aBase + SM_H * 4 + ci * 2304 + t * 16;
        #pragma unroll
        for (int gg = 0; gg < 8; gg++)
            sts128(aH + gg * 288, Hc2[gg * 2], Hc2[gg * 2 + 1]);
    }
    __syncwarp();

    // --- j-split epilogue: half-warp h covers j in [32h, 32h+32) for BOTH of
    //     its warp's centers; exchange partials via shfl_xor(16). ---
    const int wnum = tid >> 5;
    const int h    = (tid >> 4) & 1;
    const int jb   = h * 32;
    ull pA0 = 0, pA1 = 0, pB0 = 0, pB1 = 0;
    {
        const float* hr0 = s_H + (wnum * 2 + 0) * 576 + g * 72 + jb;
        const float* hr1 = s_H + (wnum * 2 + 1) * 576 + g * 72 + jb;
        const float* pwb = pe_w2 + t * 4 + jb * 64;
        #pragma unroll 4
        for (int j4 = 0; j4 < 8; j4++) {
            float4 hA = *(const float4*)(hr0 + j4 * 4);
            float4 hB = *(const float4*)(hr1 + j4 * 4);
            ull p0, p1, hp;
            ldg128(p0, p1, pwb + (j4 * 4 + 0) * 64);
            hp = pack2(hA.x, hA.x); ffma2(pA0, hp, p0, pA0); ffma2(pA1, hp, p1, pA1);
            hp = pack2(hB.x, hB.x); ffma2(pB0, hp, p0, pB0); ffma2(pB1, hp, p1, pB1);
            ldg128(p0, p1, pwb + (j4 * 4 + 1) * 64);
            hp = pack2(hA.y, hA.y); ffma2(pA0, hp, p0, pA0); ffma2(pA1, hp, p1, pA1);
            hp = pack2(hB.y, hB.y); ffma2(pB0, hp, p0, pB0); ffma2(pB1, hp, p1, pB1);
            ldg128(p0, p1, pwb + (j4 * 4 + 2) * 64);
            hp = pack2(hA.z, hA.z); ffma2(pA0, hp, p0, pA0); ffma2(pA1, hp, p1, pA1);
            hp = pack2(hB.z, hB.z); ffma2(pB0, hp, p0, pB0); ffma2(pB1, hp, p1, pB1);
            ldg128(p0, p1, pwb + (j4 * 4 + 3) * 64);
            hp = pack2(hA.w, hA.w); ffma2(pA0, hp, p0, pA0); ffma2(pA1, hp, p1, pA1);
            hp = pack2(hB.w, hB.w); ffma2(pB0, hp, p0, pB0); ffma2(pB1, hp, p1, pB1);
        }
    }
    ull own0 = h ? pB0 : pA0, own1 = h ? pB1 : pA1;
    ull oth0 = h ? pA0 : pB0, oth1 = h ? pA1 : pB1;
    ull r0 = __shfl_xor_sync(FULL, oth0, 16);
    ull r1 = __shfl_xor_sync(FULL, oth1, 16);
    ull pr0, pr1;
    fadd2(pr0, own0, r0);
    fadd2(pr1, own1, r1);
    fadd2(pr0, pr0, pack2(__ldg(pe_b2 + t * 4 + 0), __ldg(pe_b2 + t * 4 + 1)));
    fadd2(pr1, pr1, pack2(__ldg(pe_b2 + t * 4 + 2), __ldg(pe_b2 + t * 4 + 3)));
    __syncthreads();   // all warps done with s_H — safe to overlay s_out

    // --- stage output [o][m_local] for coalesced [B,O,M] writes ---
    float* s_out = s_H;   // 64 x 9 overlay
    {
        float2 a0 = unpack2(onv2[0]), a1 = unpack2(onv2[1]);
        float2 q0 = unpack2(pr0),     q1 = unpack2(pr1);
        s_out[(t * 4 + 0) * 9 + ci] = a0.x + q0.x;
        s_out[(t * 4 + 1) * 9 + ci] = a0.y + q0.y;
        s_out[(t * 4 + 2) * 9 + ci] = a1.x + q1.x;
        s_out[(t * 4 + 3) * 9 + ci] = a1.y + q1.y;
    }
    __syncthreads();

    const int m0 = gidBase & (PM - 1);
    float* ob = out + (size_t)(gidBase >> 14) * PO * PM + m0;
    #pragma unroll
    for (int q = 0; q < 4; q++) {
        int lin = q * 128 + tid;
        int o = lin >> 3;
        int ml = lin & 7;
        ob[(size_t)o * PM + ml] = s_out[o * 9 + ml];
    }
}

// ---------------------------------------------------------------------------
extern "C" void kernel_launch(void* const* d_in, const int* in_sizes, int n_in,
                              void* d_out, int out_size) {
    (void)in_sizes; (void)n_in; (void)out_size;
    const float* center_pos = (const float*)d_in[0];
    const float* center_fea = (const float*)d_in[1];
    const float* pos        = (const float*)d_in[2];
    const float* fea        = (const float*)d_in[3];
    const int*   idx        = (const int*)d_in[4];
    const float* Wq  = (const float*)d_in[5];
    const float* bq  = (const float*)d_in[6];
    const float* Wk  = (const float*)d_in[7];
    const float* bk  = (const float*)d_in[8];
    const float* Wv  = (const float*)d_in[9];
    const float* bv  = (const float*)d_in[10];
    const float* cpe_w1 = (const float*)d_in[11];
    const float* cpe_s  = (const float*)d_in[12];
    const float* cpe_b  = (const float*)d_in[13];
    const float* cpe_w2 = (const float*)d_in[14];
    const float* cpe_b2 = (const float*)d_in[15];
    const float* pe_w1  = (const float*)d_in[16];
    const float* pe_s   = (const float*)d_in[17];
    const float* pe_b   = (const float*)d_in[18];
    const float* pe_w2  = (const float*)d_in[19];
    const float* pe_b2  = (const float*)d_in[20];
    const float* we_w1  = (const float*)d_in[21];
    const float* we_s   = (const float*)d_in[22];
    const float* we_b   = (const float*)d_in[23];
    const float* we_w2  = (const float*)d_in[24];
    const float* we_b2  = (const float*)d_in[25];
    float* out = (float*)d_out;

    pc_kernel<<<768, 128>>>(fea, Wv, bv, Wq, bq, Wk, bk,
                            cpe_w1, cpe_s, cpe_b, cpe_w2, cpe_b2,
                            we_w1, we_s, we_b, center_pos, center_fea);

    const int smem = SM_TOT * 4;   // ~28.3 KB
    cudaFuncSetAttribute(attn_kernel, cudaFuncAttributeMaxDynamicSharedMemorySize, smem);
    attn_kernel<<<(PB * PM) / 8, 128, smem>>>(center_pos, pos, idx,
                                              pe_w1, pe_s, pe_w2, pe_b, pe_b2,
                                              we_w2, we_b2, out);
}

// round 16
// speedup vs baseline: 1.1788x; 1.0452x over previous
#include <cuda_runtime.h>
#include <cuda_fp16.h>
#include <cstddef>
#include <cstdint>

// Problem constants
#define PB 4
#define PN 16384
#define PM 16384
#define PK 16
#define PC 64
#define PO 64
#define PG 8

typedef unsigned long long ull;

// ---- f32x2 packed helpers (sm_103a FFMA2 path) ----
__device__ __forceinline__ void ffma2(ull& d, ull a, ull b, ull c) {
    asm("fma.rn.f32x2 %0, %1, %2, %3;" : "=l"(d) : "l"(a), "l"(b), "l"(c));
}
__device__ __forceinline__ void fadd2(ull& d, ull a, ull b) {
    asm("add.rn.f32x2 %0, %1, %2;" : "=l"(d) : "l"(a), "l"(b));
}
__device__ __forceinline__ ull pack2(float lo, float hi) {
    ull r; asm("mov.b64 %0, {%1, %2};" : "=l"(r) : "f"(lo), "f"(hi)); return r;
}
__device__ __forceinline__ ull packu2(uint32_t lo, uint32_t hi) {
    ull r; asm("mov.b64 %0, {%1, %2};" : "=l"(r) : "r"(lo), "r"(hi)); return r;
}
__device__ __forceinline__ float2 unpack2(ull v) {
    float2 f; asm("mov.b64 {%0, %1}, %2;" : "=f"(f.x), "=f"(f.y) : "l"(v)); return f;
}
__device__ __forceinline__ ull lds64(uint32_t a) {
    ull r; asm volatile("ld.shared.b64 %0, [%1];" : "=l"(r) : "r"(a)); return r;
}
__device__ __forceinline__ void lds128(ull& x, ull& y, uint32_t a) {
    asm volatile("ld.shared.v2.b64 {%0,%1}, [%2];" : "=l"(x), "=l"(y) : "r"(a));
}
__device__ __forceinline__ void sts128(uint32_t a, ull x, ull y) {
    asm volatile("st.shared.v2.b64 [%0], {%1,%2};" :: "r"(a), "l"(x), "l"(y) : "memory");
}
__device__ __forceinline__ void ldg128(ull& x, ull& y, const void* p) {
    asm volatile("ld.global.nc.v2.b64 {%0,%1}, [%2];" : "=l"(x), "=l"(y) : "l"(p));
}
__device__ __forceinline__ ull ldg64(const void* p) {
    ull r; asm volatile("ld.global.nc.b64 %0, [%1];" : "=l"(r) : "l"(p)); return r;
}
__device__ __forceinline__ void stg128(void* p, ull x, ull y) {
    asm volatile("st.global.v2.b64 [%0], {%1,%2};" :: "l"(p), "l"(x), "l"(y) : "memory");
}
// fp32 pair -> fp16x2 (RN)
__device__ __forceinline__ uint32_t f2h2(ull v) {
    float2 f = unpack2(v);
    __half2 h = __float22half2_rn(make_float2(f.x, f.y));
    return *(uint32_t*)&h;
}

static __device__ __half g_xvh[PB * PN * PO];  // x_v [B,N,64] in fp16 (gather bytes halved)
static __device__ float g_a [PB * PN * PG];    // per-point logit precursor [B,N,8] (fp32)
static __device__ float g_c [PB * PM * PG];    // per-center logit precursor [B,M,8]

// ---------------------------------------------------------------------------
// Kernel 1+2 merged; in-block folds from coalesced smem staging (R15).
// blocks [0,256): per-point precompute (2 pts/thread)
// blocks [256,768): per-center precompute (1 center/thread)
// ---------------------------------------------------------------------------
__global__ void __launch_bounds__(128, 2)
pc_kernel(const float* __restrict__ fea,
          const float* __restrict__ Wv,
          const float* __restrict__ bv,
          const float* __restrict__ Wq, const float* __restrict__ bq,
          const float* __restrict__ Wk, const float* __restrict__ bk,
          const float* __restrict__ cpe_w1, const float* __restrict__ cpe_s,
          const float* __restrict__ cpe_b,
          const float* __restrict__ cpe_w2, const float* __restrict__ cpe_b2,
          const float* __restrict__ we_w1, const float* __restrict__ we_s,
          const float* __restrict__ we_b,
          const float* __restrict__ center_pos,
          const float* __restrict__ center_fea) {
    __shared__ float su[10504];    // 42 KB: max(point 9544, center 10504)
    int tid = threadIdx.x;

    if (blockIdx.x < 256) {
        // ---------------- point path ----------------
        float* sWv  = su;            // 4096
        float* sWka = su + 4096;     // 512
        float* sbv  = su + 4608;     // 64
        float* sa0  = su + 4672;     // 8
        float* sWW  = su + 4680;     // 512 (we_w1)
        float* sWk  = su + 5192;     // 64 rows x stride 68 = 4352
        for (int i = tid; i < 4096; i += 128) sWv[i] = Wv[i];
        for (int i = tid; i < 4096; i += 128) {
            int c = i >> 6, o = i & 63;
            sWk[c * 68 + o] = Wk[i];
        }
        *(float4*)(sWW + tid * 4) = *(const float4*)(we_w1 + tid * 4);
        if (tid < 64) sbv[tid] = bv[tid];
        __syncthreads();

        uint32_t aWW = (uint32_t)__cvta_generic_to_shared(sWW);

        // fold from smem: sWka[c*8+g] = (Wk[c,:]·we_w1[:,g]) * we_s[g]
        {
            int c  = tid >> 1;
            int g0 = (tid & 1) * 4;
            ull acc01 = 0ull, acc23 = 0ull;
            #pragma unroll 8
            for (int o = 0; o < 64; o++) {
                float w = sWk[c * 68 + o];
                ull w01, w23;
                lds128(w01, w23, aWW + o * 32 + g0 * 4);
                ull hp = pack2(w, w);
                ffma2(acc01, hp, w01, acc01);
                ffma2(acc23, hp, w23, acc23);
            }
            float2 a01 = unpack2(acc01), a23 = unpack2(acc23);
            sWka[c * 8 + g0 + 0] = a01.x * __ldg(we_s + g0 + 0);
            sWka[c * 8 + g0 + 1] = a01.y * __ldg(we_s + g0 + 1);
            sWka[c * 8 + g0 + 2] = a23.x * __ldg(we_s + g0 + 2);
            sWka[c * 8 + g0 + 3] = a23.y * __ldg(we_s + g0 + 3);
        }
        if (tid < 8) {
            float a0 = 0.f;
            #pragma unroll 8
            for (int o = 0; o < 64; o++)
                a0 = fmaf(__ldg(bk + o), sWW[o * 8 + tid], a0);
            sa0[tid] = a0 * __ldg(we_s + tid);
        }
        __syncthreads();

        uint32_t aWv = (uint32_t)__cvta_generic_to_shared(sWv);
        uint32_t aKa = (uint32_t)__cvta_generic_to_shared(sWka);
        uint32_t aBv = (uint32_t)__cvta_generic_to_shared(sbv);
        uint32_t aA0 = (uint32_t)__cvta_generic_to_shared(sa0);

        int gp0 = (blockIdx.x * 128 + tid) * 2;   // two adjacent points
        int b = gp0 >> 14;
        int n = gp0 & (PN - 1);
        const float* fp = fea + (size_t)b * PC * PN + n;

        ull accA[32], accB[32];
        ull agA[4],  agB[4];
        #pragma unroll
        for (int i = 0; i < 32; i++) { accA[i] = lds64(aBv + i * 8); accB[i] = accA[i]; }
        #pragma unroll
        for (int i = 0; i < 4; i++)  { agA[i]  = lds64(aA0 + i * 8); agB[i] = agA[i]; }

        #pragma unroll 2
        for (int c = 0; c < 64; c++) {
            float2 f2 = *(const float2*)(fp + (size_t)c * PN);
            ull fA = pack2(f2.x, f2.x);
            ull fB = pack2(f2.y, f2.y);
            uint32_t rowa = aWv + c * 256;
            #pragma unroll
            for (int p = 0; p < 16; p++) {
                ull w0, w1;
                lds128(w0, w1, rowa + p * 16);
                ffma2(accA[p * 2 + 0], fA, w0, accA[p * 2 + 0]);
                ffma2(accA[p * 2 + 1], fA, w1, accA[p * 2 + 1]);
                ffma2(accB[p * 2 + 0], fB, w0, accB[p * 2 + 0]);
                ffma2(accB[p * 2 + 1], fB, w1, accB[p * 2 + 1]);
            }
            ull k0, k1, k2, k3;
            lds128(k0, k1, aKa + c * 32);
            lds128(k2, k3, aKa + c * 32 + 16);
            ffma2(agA[0], fA, k0, agA[0]);  ffma2(agA[1], fA, k1, agA[1]);
            ffma2(agA[2], fA, k2, agA[2]);  ffma2(agA[3], fA, k3, agA[3]);
            ffma2(agB[0], fB, k0, agB[0]);  ffma2(agB[1], fB, k1, agB[1]);
            ffma2(agB[2], fB, k2, agB[2]);  ffma2(agB[3], fB, k3, agB[3]);
        }

        // fp16 x_v stores: 64 halves = 128 B per point = 8 stg128
        __half* ovA = g_xvh + (size_t)gp0 * 64;
        __half* ovB = ovA + 64;
        #pragma unroll
        for (int p = 0; p < 8; p++) {
            ull xa = packu2(f2h2(accA[p * 4 + 0]), f2h2(accA[p * 4 + 1]));
            ull ya = packu2(f2h2(accA[p * 4 + 2]), f2h2(accA[p * 4 + 3]));
            stg128(ovA + p * 8, xa, ya);
            ull xb = packu2(f2h2(accB[p * 4 + 0]), f2h2(accB[p * 4 + 1]));
            ull yb = packu2(f2h2(accB[p * 4 + 2]), f2h2(accB[p * 4 + 3]));
            stg128(ovB + p * 8, xb, yb);
        }
        float* avA = g_a + (size_t)gp0 * 8;
        stg128(avA,      agA[0], agA[1]);
        stg128(avA + 4,  agA[2], agA[3]);
        stg128(avA + 8,  agB[0], agB[1]);
        stg128(avA + 12, agB[2], agB[3]);
    } else {
        // ---------------- center path ----------------
        float* sWqa = su;            // 512
        float* sWca = su + 512;      // 512
        float* sw1  = su + 1024;     // 192
        float* sb1  = su + 1216;     // 64
        float* sc0  = su + 1280;     // 8
        float* sWW  = su + 1288;     // 512
        float* sWq  = su + 1800;     // 4352 (stride 68)
        float* sWc  = su + 6152;     // 4352 (stride 68)
        for (int i = tid; i < 4096; i += 128) {
            int c = i >> 6, o = i & 63;
            sWq[c * 68 + o] = Wq[i];
            sWc[c * 68 + o] = cpe_w2[i];
        }
        *(float4*)(sWW + tid * 4) = *(const float4*)(we_w1 + tid * 4);
        for (int i = tid; i < 192; i += 128) {
            int j = i % 64;
            sw1[i] = cpe_w1[i] * cpe_s[j];
        }
        if (tid < 64) sb1[tid] = cpe_b[tid];
        __syncthreads();

        uint32_t aWW = (uint32_t)__cvta_generic_to_shared(sWW);

        // fold both Wq and cpe_w2 against we_w1 (smem-resident, coalesced)
        {
            int c  = tid >> 1;
            int g0 = (tid & 1) * 4;
            ull aq01 = 0ull, aq23 = 0ull, ac01 = 0ull, ac23 = 0ull;
            #pragma unroll 8
            for (int o = 0; o < 64; o++) {
                float wq = sWq[c * 68 + o];
                float wc = sWc[c * 68 + o];
                ull w01, w23;
                lds128(w01, w23, aWW + o * 32 + g0 * 4);
                ull hq = pack2(wq, wq);
                ull hc = pack2(wc, wc);
                ffma2(aq01, hq, w01, aq01);
                ffma2(aq23, hq, w23, aq23);
                ffma2(ac01, hc, w01, ac01);
                ffma2(ac23, hc, w23, ac23);
            }
            float2 q01 = unpack2(aq01), q23 = unpack2(aq23);
            float2 c01 = unpack2(ac01), c23 = unpack2(ac23);
            float s0 = __ldg(we_s + g0 + 0), s1 = __ldg(we_s + g0 + 1);
            float s2 = __ldg(we_s + g0 + 2), s3 = __ldg(we_s + g0 + 3);
            sWqa[c * 8 + g0 + 0] = q01.x * s0;
            sWqa[c * 8 + g0 + 1] = q01.y * s1;
            sWqa[c * 8 + g0 + 2] = q23.x * s2;
            sWqa[c * 8 + g0 + 3] = q23.y * s3;
            sWca[c * 8 + g0 + 0] = c01.x * s0;
            sWca[c * 8 + g0 + 1] = c01.y * s1;
            sWca[c * 8 + g0 + 2] = c23.x * s2;
            sWca[c * 8 + g0 + 3] = c23.y * s3;
        }
        if (tid < 8) {
            float c0 = 0.f;
            #pragma unroll 8
            for (int o = 0; o < 64; o++)
                c0 = fmaf(__ldg(bq + o) - __ldg(cpe_b2 + o), sWW[o * 8 + tid], c0);
            sc0[tid] = c0 * __ldg(we_s + tid) - __ldg(we_b + tid);
        }
        __syncthreads();

        int gid = (blockIdx.x - 256) * 128 + tid;
        float px = center_pos[(size_t)gid * 3 + 0];
        float py = center_pos[(size_t)gid * 3 + 1];
        float pz = center_pos[(size_t)gid * 3 + 2];

        float acc[8];
        #pragma unroll
        for (int g = 0; g < 8; g++) acc[g] = sc0[g];

        int b = gid >> 14;
        int m = gid & (PM - 1);
        const float* cf = center_fea + (size_t)b * PC * PM + m;
        #pragma unroll 4
        for (int i = 0; i < 64; i++) {
            float h = fmaxf(fmaf(px, sw1[i], fmaf(py, sw1[64 + i], fmaf(pz, sw1[128 + i], sb1[i]))), 0.f);
            float f = cf[(size_t)i * PM];
            const float4* qa = (const float4*)(sWqa + i * 8);
            const float4* ca = (const float4*)(sWca + i * 8);
            float4 q0 = qa[0], q1 = qa[1], c0 = ca[0], c1 = ca[1];
            acc[0] += f * q0.x - h * c0.x;  acc[1] += f * q0.y - h * c0.y;
            acc[2] += f * q0.z - h * c0.z;  acc[3] += f * q0.w - h * c0.w;
            acc[4] += f * q1.x - h * c1.x;  acc[5] += f * q1.y - h * c1.y;
            acc[6] += f * q1.z - h * c1.z;  acc[7] += f * q1.w - h * c1.w;
        }
        float4* cv = (float4*)(g_c + (size_t)gid * 8);
        cv[0] = make_float4(acc[0], acc[1], acc[2], acc[3]);
        cv[1] = make_float4(acc[4], acc[5], acc[6], acc[7]);
    }
}

// ---------------------------------------------------------------------------
// Kernel 3: main attention — identical to R15 except the v-gather reads fp16
// x_v (128 B/point: half the lines/bytes) and converts in registers.
// ---------------------------------------------------------------------------
// smem float layout:
//   0     s_we2  [64]
//   64    s_web2 [8]
//   72    s_ikd  [8*16 float4] = 512
//   584   s_w    [8*16*16] = 2048      duplicated {w,w} pairs
//   2632  s_H    [8 * 576]             8 rows x 72 floats per center
#define SM_WE2   0
#define SM_WEB2  64
#define SM_IKD   72
#define SM_W     584
#define SM_H     2632
#define SM_TOT   (2632 + 8 * 576)

__global__ void __launch_bounds__(128, 5)
attn_kernel(const float* __restrict__ center_pos,
            const float* __restrict__ pos,
            const int* __restrict__ idx,
            const float* __restrict__ pe_w1,
            const float* __restrict__ pe_s,
            const float* __restrict__ pe_w2,
            const float* __restrict__ pe_b,
            const float* __restrict__ pe_b2,
            const float* __restrict__ we_w2,
            const float* __restrict__ we_b2,
            float* __restrict__ out) {
    extern __shared__ float sm[];
    float*  s_we2  = sm + SM_WE2;
    float*  s_web2 = sm + SM_WEB2;
    float4* s_ikd  = (float4*)(sm + SM_IKD);
    float4* s_w4   = (float4*)(sm + SM_W);
    float*  s_H    = sm + SM_H;

    const int tid = threadIdx.x;
    if (tid < 64) s_we2[tid] = we_w2[tid];
    if (tid < 8)  s_web2[tid] = we_b2[tid];
    __syncthreads();

    const unsigned FULL = 0xffffffffu;
    const int ci = tid >> 4;           // center within block (0..7)
    const int t  = tid & 15;           // lane within center
    const int g  = t >> 1;             // my output group
    const int gidBase = blockIdx.x * 8;
    const int gid = gidBase + ci;
    const int b = gid >> 14;

    const uint32_t aBase = (uint32_t)__cvta_generic_to_shared(sm);
    const uint32_t aW    = aBase + SM_W * 4 + ci * 1024;   // this center's w-pairs

    // --- prologue: my edge (k = t) ---
    int myik;
    {
        int ik = idx[(size_t)gid * 16 + t];
        myik = b * PN + ik;
        const float* pp = pos + (size_t)myik * 3;
        float cx = center_pos[(size_t)gid * 3 + 0];
        float cy = center_pos[(size_t)gid * 3 + 1];
        float cz = center_pos[(size_t)gid * 3 + 2];
        s_ikd[ci * 16 + t] = make_float4(pp[0] - cx, pp[1] - cy, pp[2] - cz,
                                         __int_as_float(myik));
    }

    // --- logits + softmax for my edge ---
    {
        const float4* cpv = (const float4*)(g_c + (size_t)gid * 8);
        float4 cA = cpv[0], cB = cpv[1];
        const float4* ap = (const float4*)(g_a + (size_t)myik * 8);
        float4 a0 = ap[0], a1 = ap[1];
        float h1[8];
        h1[0] = fmaxf(a0.x - cA.x, 0.f); h1[1] = fmaxf(a0.y - cA.y, 0.f);
        h1[2] = fmaxf(a0.z - cA.z, 0.f); h1[3] = fmaxf(a0.w - cA.w, 0.f);
        h1[4] = fmaxf(a1.x - cB.x, 0.f); h1[5] = fmaxf(a1.y - cB.y, 0.f);
        h1[6] = fmaxf(a1.z - cB.z, 0.f); h1[7] = fmaxf(a1.w - cB.w, 0.f);

        float4 b0 = *(const float4*)(s_web2);
        float4 b1 = *(const float4*)(s_web2 + 4);
        float lg[8] = {b0.x, b0.y, b0.z, b0.w, b1.x, b1.y, b1.z, b1.w};
        #pragma unroll
        for (int gp = 0; gp < 8; gp++) {
            float hv = h1[gp];
            float4 wa = *(const float4*)(s_we2 + gp * 8);
            float4 wb = *(const float4*)(s_we2 + gp * 8 + 4);
            lg[0] = fmaf(hv, wa.x, lg[0]); lg[1] = fmaf(hv, wa.y, lg[1]);
            lg[2] = fmaf(hv, wa.z, lg[2]); lg[3] = fmaf(hv, wa.w, lg[3]);
            lg[4] = fmaf(hv, wb.x, lg[4]); lg[5] = fmaf(hv, wb.y, lg[5]);
            lg[6] = fmaf(hv, wb.z, lg[6]); lg[7] = fmaf(hv, wb.w, lg[7]);
        }
        float mx[8];
        #pragma unroll
        for (int gg = 0; gg < 8; gg++) mx[gg] = lg[gg];
        #pragma unroll
        for (int s = 1; s < 16; s <<= 1)
            #pragma unroll
            for (int gg = 0; gg < 8; gg++)
                mx[gg] = fmaxf(mx[gg], __shfl_xor_sync(FULL, mx[gg], s, 16));
        float e[8], sum[8];
        #pragma unroll
        for (int gg = 0; gg < 8; gg++) { e[gg] = __expf(lg[gg] - mx[gg]); sum[gg] = e[gg]; }
        #pragma unroll
        for (int s = 1; s < 16; s <<= 1)
            #pragma unroll
            for (int gg = 0; gg < 8; gg++)
                sum[gg] += __shfl_xor_sync(FULL, sum[gg], s, 16);
        #pragma unroll
        for (int gg = 0; gg < 8; gg++)
            e[gg] *= __fdividef(1.f, sum[gg]);
        float4* wb4 = s_w4 + (ci * 16 + t) * 4;
        wb4[0] = make_float4(e[0], e[0], e[1], e[1]);
        wb4[1] = make_float4(e[2], e[2], e[3], e[3]);
        wb4[2] = make_float4(e[4], e[4], e[5], e[5]);
        wb4[3] = make_float4(e[6], e[6], e[7], e[7]);
    }
    __syncwarp();

    // --- per-thread pe_w1 slice (folded with pe_s inline) + bias ---
    float wxa[4], wxb[4], wxc[4], bb[4];
    #pragma unroll
    for (int jj = 0; jj < 4; jj++) {
        float ps = __ldg(pe_s + t * 4 + jj);
        wxa[jj] = __ldg(pe_w1 + 0 * 64 + t * 4 + jj) * ps;
        wxb[jj] = __ldg(pe_w1 + 1 * 64 + t * 4 + jj) * ps;
        wxc[jj] = __ldg(pe_w1 + 2 * 64 + t * 4 + jj) * ps;
        bb[jj]  = __ldg(pe_b + t * 4 + jj);
    }

    // --- edge loop ---
    ull Hc2[16];           // Hc2[gg*2+p] = {H[gg][j-pair p]}
    ull onv2[2] = {0ull, 0ull};
    #pragma unroll
    for (int i = 0; i < 16; i++) Hc2[i] = 0ull;

    #pragma unroll
    for (int k = 0; k < 16; k++) {
        float4 d = *(float4*)((char*)sm + (SM_IKD * 4 + ci * 256 + k * 16));
        int ikk = __float_as_int(d.w);
        ull wp0, wp1, wp2, wp3, wp4, wp5, wp6, wp7;
        lds128(wp0, wp1, aW + k * 64);
        lds128(wp2, wp3, aW + k * 64 + 16);
        lds128(wp4, wp5, aW + k * 64 + 32);
        lds128(wp6, wp7, aW + k * 64 + 48);
        ull wtp = lds64(aW + k * 64 + g * 8);
        // fp16 v gather: 4 halves = 8 B per lane (1 line per center)
        ull vv = ldg64(g_xvh + (size_t)ikk * 64 + t * 4);
        uint32_t vlo, vhi;
        asm("mov.b64 {%0,%1}, %2;" : "=r"(vlo), "=r"(vhi) : "l"(vv));
        float2 fa = __half22float2(*(__half2*)&vlo);
        float2 fb = __half22float2(*(__half2*)&vhi);
        ull v0 = pack2(fa.x, fa.y);
        ull v1 = pack2(fb.x, fb.y);

        float h0 = fmaxf(fmaf(d.x, wxa[0], fmaf(d.y, wxb[0], fmaf(d.z, wxc[0], bb[0]))), 0.f);
        float h1 = fmaxf(fmaf(d.x, wxa[1], fmaf(d.y, wxb[1], fmaf(d.z, wxc[1], bb[1]))), 0.f);
        float h2 = fmaxf(fmaf(d.x, wxa[2], fmaf(d.y, wxb[2], fmaf(d.z, wxc[2], bb[2]))), 0.f);
        float h3 = fmaxf(fmaf(d.x, wxa[3], fmaf(d.y, wxb[3], fmaf(d.z, wxc[3], bb[3]))), 0.f);
        ull h01 = pack2(h0, h1);
        ull h23 = pack2(h2, h3);

        ffma2(Hc2[0],  wp0, h01, Hc2[0]);  ffma2(Hc2[1],  wp0, h23, Hc2[1]);
        ffma2(Hc2[2],  wp1, h01, Hc2[2]);  ffma2(Hc2[3],  wp1, h23, Hc2[3]);
        ffma2(Hc2[4],  wp2, h01, Hc2[4]);  ffma2(Hc2[5],  wp2, h23, Hc2[5]);
        ffma2(Hc2[6],  wp3, h01, Hc2[6]);  ffma2(Hc2[7],  wp3, h23, Hc2[7]);
        ffma2(Hc2[8],  wp4, h01, Hc2[8]);  ffma2(Hc2[9],  wp4, h23, Hc2[9]);
        ffma2(Hc2[10], wp5, h01, Hc2[10]); ffma2(Hc2[11], wp5, h23, Hc2[11]);
        ffma2(Hc2[12], wp6, h01, Hc2[12]); ffma2(Hc2[13], wp6, h23, Hc2[13]);
        ffma2(Hc2[14], wp7, h01, Hc2[14]); ffma2(Hc2[15], wp7, h23, Hc2[15]);

        ffma2(onv2[0], wtp, v0, onv2[0]);
        ffma2(onv2[1], wtp, v1, onv2[1]);
    }

    // --- H transpose through smem (warp-local) ---
    {
        uint32_t aH = aBase + SM_H * 4 + ci * 2304 + t * 16;
        #pragma unroll
        for (int gg = 0; gg < 8; gg++)
            sts128(aH + gg * 288, Hc2[gg * 2], Hc2[gg * 2 + 1]);
    }
    __syncwarp();

    // --- j-split epilogue: half-warp h covers j in [32h, 32h+32) for BOTH of
    //     its warp's centers; exchange partials via shfl_xor(16). ---
    const int wnum = tid >> 5;
    const int h    = (tid >> 4) & 1;
    const int jb   = h * 32;
    ull pA0 = 0, pA1 = 0, pB0 = 0, pB1 = 0;
    {
        const float* hr0 = s_H + (wnum * 2 + 0) * 576 + g * 72 + jb;
        const float* hr1 = s_H + (wnum * 2 + 1) * 576 + g * 72 + jb;
        const float* pwb = pe_w2 + t * 4 + jb * 64;
        #pragma unroll 4
        for (int j4 = 0; j4 < 8; j4++) {
            float4 hA = *(const float4*)(hr0 + j4 * 4);
            float4 hB = *(const float4*)(hr1 + j4 * 4);
            ull p0, p1, hp;
            ldg128(p0, p1, pwb + (j4 * 4 + 0) * 64);
            hp = pack2(hA.x, hA.x); ffma2(pA0, hp, p0, pA0); ffma2(pA1, hp, p1, pA1);
            hp = pack2(hB.x, hB.x); ffma2(pB0, hp, p0, pB0); ffma2(pB1, hp, p1, pB1);
            ldg128(p0, p1, pwb + (j4 * 4 + 1) * 64);
            hp = pack2(hA.y, hA.y); ffma2(pA0, hp, p0, pA0); ffma2(pA1, hp, p1, pA1);
            hp = pack2(hB.y, hB.y); ffma2(pB0, hp, p0, pB0); ffma2(pB1, hp, p1, pB1);
            ldg128(p0, p1, pwb + (j4 * 4 + 2) * 64);
            hp = pack2(hA.z, hA.z); ffma2(pA0, hp, p0, pA0); ffma2(pA1, hp, p1, pA1);
            hp = pack2(hB.z, hB.z); ffma2(pB0, hp, p0, pB0); ffma2(pB1, hp, p1, pB1);
            ldg128(p0, p1, pwb + (j4 * 4 + 3) * 64);
            hp = pack2(hA.w, hA.w); ffma2(pA0, hp, p0, pA0); ffma2(pA1, hp, p1, pA1);
            hp = pack2(hB.w, hB.w); ffma2(pB0, hp, p0, pB0); ffma2(pB1, hp, p1, pB1);
        }
    }
    ull own0 = h ? pB0 : pA0, own1 = h ? pB1 : pA1;
    ull oth0 = h ? pA0 : pB0, oth1 = h ? pA1 : pB1;
    ull r0 = __shfl_xor_sync(FULL, oth0, 16);
    ull r1 = __shfl_xor_sync(FULL, oth1, 16);
    ull pr0, pr1;
    fadd2(pr0, own0, r0);
    fadd2(pr1, own1, r1);
    fadd2(pr0, pr0, pack2(__ldg(pe_b2 + t * 4 + 0), __ldg(pe_b2 + t * 4 + 1)));
    fadd2(pr1, pr1, pack2(__ldg(pe_b2 + t * 4 + 2), __ldg(pe_b2 + t * 4 + 3)));
    __syncthreads();   // all warps done with s_H — safe to overlay s_out

    // --- stage output [o][m_local] for coalesced [B,O,M] writes ---
    float* s_out = s_H;   // 64 x 9 overlay
    {
        float2 a0 = unpack2(onv2[0]), a1 = unpack2(onv2[1]);
        float2 q0 = unpack2(pr0),     q1 = unpack2(pr1);
        s_out[(t * 4 + 0) * 9 + ci] = a0.x + q0.x;
        s_out[(t * 4 + 1) * 9 + ci] = a0.y + q0.y;
        s_out[(t * 4 + 2) * 9 + ci] = a1.x + q1.x;
        s_out[(t * 4 + 3) * 9 + ci] = a1.y + q1.y;
    }
    __syncthreads();

    const int m0 = gidBase & (PM - 1);
    float* ob = out + (size_t)(gidBase >> 14) * PO * PM + m0;
    #pragma unroll
    for (int q = 0; q < 4; q++) {
        int lin = q * 128 + tid;
        int o = lin >> 3;
        int ml = lin & 7;
        ob[(size_t)o * PM + ml] = s_out[o * 9 + ml];
    }
}

// ---------------------------------------------------------------------------
extern "C" void kernel_launch(void* const* d_in, const int* in_sizes, int n_in,
                              void* d_out, int out_size) {
    (void)in_sizes; (void)n_in; (void)out_size;
    const float* center_pos = (const float*)d_in[0];
    const float* center_fea = (const float*)d_in[1];
    const float* pos        = (const float*)d_in[2];
    const float* fea        = (const float*)d_in[3];
    const int*   idx        = (const int*)d_in[4];
    const float* Wq  = (const float*)d_in[5];
    const float* bq  = (const float*)d_in[6];
    const float* Wk  = (const float*)d_in[7];
    const float* bk  = (const float*)d_in[8];
    const float* Wv  = (const float*)d_in[9];
    const float* bv  = (const float*)d_in[10];
    const float* cpe_w1 = (const float*)d_in[11];
    const float* cpe_s  = (const float*)d_in[12];
    const float* cpe_b  = (const float*)d_in[13];
    const float* cpe_w2 = (const float*)d_in[14];
    const float* cpe_b2 = (const float*)d_in[15];
    const float* pe_w1  = (const float*)d_in[16];
    const float* pe_s   = (const float*)d_in[17];
    const float* pe_b   = (const float*)d_in[18];
    const float* pe_w2  = (const float*)d_in[19];
    const float* pe_b2  = (const float*)d_in[20];
    const float* we_w1  = (const float*)d_in[21];
    const float* we_s   = (const float*)d_in[22];
    const float* we_b   = (const float*)d_in[23];
    const float* we_w2  = (const float*)d_in[24];
    const float* we_b2  = (const float*)d_in[25];
    float* out = (float*)d_out;

    pc_kernel<<<768, 128>>>(fea, Wv, bv, Wq, bq, Wk, bk,
                            cpe_w1, cpe_s, cpe_b, cpe_w2, cpe_b2,
                            we_w1, we_s, we_b, center_pos, center_fea);

    const int smem = SM_TOT * 4;   // ~28.3 KB
    cudaFuncSetAttribute(attn_kernel, cudaFuncAttributeMaxDynamicSharedMemorySize, smem);
    attn_kernel<<<(PB * PM) / 8, 128, smem>>>(center_pos, pos, idx,
                                              pe_w1, pe_s, pe_w2, pe_b, pe_b2,
                                              we_w2, we_b2, out);
}